// round 13
// baseline (speedup 1.0000x reference)
#include <cuda_runtime.h>
#include <cuda_bf16.h>
#include <cstdint>

#define N_NODES 100000
#define IN_CH   256
#define OUT_CH  64
#define NNZ_MAX 1600000
#define SLOTS   64          // fixed edge slots per row (deg ~ Poisson(16))

// ---------------------------------------------------------------------------
// Static device scratch (no allocations allowed)
// ---------------------------------------------------------------------------
__device__ float g_Xp[(size_t)N_NODES * OUT_CH];       // fp32 projected features
__device__ int   g_idx64;
__device__ int   g_cursor[N_NODES];                    // per-row fill counters
__device__ int2  g_edge[(size_t)N_NODES * SLOTS];      // bins {colByteOff, val}
__device__ int   g_spillcnt;
__device__ int4  g_spill[NNZ_MAX];                     // overflow {row, col, val, 0}

// ---------------------------------------------------------------------------
// helpers
// ---------------------------------------------------------------------------
__device__ __forceinline__ uint32_t smem_u32(const void* p) {
    uint32_t a;
    asm("{ .reg .u64 t; cvta.to.shared.u64 t, %1; cvt.u32.u64 %0, t; }"
        : "=r"(a) : "l"(p));
    return a;
}

__device__ __forceinline__ void ldsm_x4(uint32_t* r, uint32_t addr) {
    asm volatile("ldmatrix.sync.aligned.m8n8.x4.shared.b16 {%0,%1,%2,%3}, [%4];"
                 : "=r"(r[0]), "=r"(r[1]), "=r"(r[2]), "=r"(r[3]) : "r"(addr));
}
__device__ __forceinline__ void ldsm_x2(uint32_t* r, uint32_t addr) {
    asm volatile("ldmatrix.sync.aligned.m8n8.x2.shared.b16 {%0,%1}, [%2];"
                 : "=r"(r[0]), "=r"(r[1]) : "r"(addr));
}
__device__ __forceinline__ void mma_bf16(float* c, const uint32_t* a, const uint32_t* b) {
    asm volatile(
        "mma.sync.aligned.m16n8k16.row.col.f32.bf16.bf16.f32 "
        "{%0,%1,%2,%3}, {%4,%5,%6,%7}, {%8,%9}, {%0,%1,%2,%3};"
        : "+f"(c[0]), "+f"(c[1]), "+f"(c[2]), "+f"(c[3])
        : "r"(a[0]), "r"(a[1]), "r"(a[2]), "r"(a[3]), "r"(b[0]), "r"(b[1]));
}

// split fp32 pair into (hi bf16x2, lo bf16x2): x = hi + lo exactly to ~2^-16
__device__ __forceinline__ void split2(float a, float b, uint32_t& hi, uint32_t& lo)
{
    uint32_t h;
    asm("cvt.rn.bf16x2.f32 %0, %1, %2;" : "=r"(h) : "f"(b), "f"(a)); // a->low
    __nv_bfloat162 hb = *(__nv_bfloat162*)&h;
    float2 hf = __bfloat1622float2(hb);
    float ra = a - hf.x;
    float rb = b - hf.y;
    uint32_t l;
    asm("cvt.rn.bf16x2.f32 %0, %1, %2;" : "=r"(l) : "f"(rb), "f"(ra));
    hi = h; lo = l;
}

// ---------------------------------------------------------------------------
// init: zero cursors + spill counter, detect int64-vs-int32 indices (block 0)
// ---------------------------------------------------------------------------
__global__ __launch_bounds__(256) void init_kernel(const long long* __restrict__ rows,
                                                   int nnz)
{
    int i = blockIdx.x * blockDim.x + threadIdx.x;
    if (i < N_NODES) g_cursor[i] = 0;
    if (i == 0) g_spillcnt = 0;

    if (blockIdx.x == 0) {
        __shared__ int ok;
        if (threadIdx.x == 0) ok = 1;
        __syncthreads();
        int nchk = 256;
        if (nnz < 512) nchk = nnz / 2;
        if ((int)threadIdx.x < nchk) {
            long long v = rows[threadIdx.x];
            if (v < 0 || v >= N_NODES) ok = 0;
        }
        __syncthreads();
        if (threadIdx.x == 0) g_idx64 = ok;
    }
}

// ---------------------------------------------------------------------------
// GEMM: Xp = X @ W^T via mma.sync bf16x3 (hi*hi + hi*lo + lo*hi)
// Block tile 128 x 64, 8 warps of 32x32, K chunked at 128. fp32 epilogue.
// ---------------------------------------------------------------------------
#define TILE_M 128
#define KC     128
#define AST    272
#define A_HI   0
#define A_LO   34816
#define B_HI   69632
#define B_LO   87040
#define GEMM_SMEM 104448

__global__ __launch_bounds__(256) void gemm_mma_kernel(const float* __restrict__ X,
                                                       const float* __restrict__ W)
{
    extern __shared__ char dsm[];
    const uint32_t sb = smem_u32(dsm);

    const int tid = threadIdx.x;
    const int wid = tid >> 5, lid = tid & 31;
    const int rowsBase = blockIdx.x * TILE_M;
    const int warpM = wid & 3, warpN = wid >> 2;
    const int mbase = warpM * 32, nbase = warpN * 32;

    float acc[2][4][4] = {};
    const int matid = lid >> 3, rowin = lid & 7;

    for (int kc = 0; kc < IN_CH / KC; kc++) {
        #pragma unroll 4
        for (int i = 0; i < 16; i++) {
            int idx = i * 256 + tid;
            int r = idx >> 5, kq = idx & 31;
            int node = rowsBase + r;
            float4 x = make_float4(0.f, 0.f, 0.f, 0.f);
            if (node < N_NODES)
                x = *(const float4*)&X[(size_t)node * IN_CH + kc * KC + kq * 4];
            uint32_t h0, l0, h1, l1;
            split2(x.x, x.y, h0, l0);
            split2(x.z, x.w, h1, l1);
            uint32_t off = r * AST + kq * 8;
            *(uint32_t*)(dsm + A_HI + off)     = h0;
            *(uint32_t*)(dsm + A_HI + off + 4) = h1;
            *(uint32_t*)(dsm + A_LO + off)     = l0;
            *(uint32_t*)(dsm + A_LO + off + 4) = l1;
        }
        #pragma unroll 4
        for (int i = 0; i < 8; i++) {
            int idx = i * 256 + tid;
            int r = idx >> 5, kq = idx & 31;
            float4 x = *(const float4*)&W[(size_t)r * IN_CH + kc * KC + kq * 4];
            uint32_t h0, l0, h1, l1;
            split2(x.x, x.y, h0, l0);
            split2(x.z, x.w, h1, l1);
            uint32_t off = r * AST + kq * 8;
            *(uint32_t*)(dsm + B_HI + off)     = h0;
            *(uint32_t*)(dsm + B_HI + off + 4) = h1;
            *(uint32_t*)(dsm + B_LO + off)     = l0;
            *(uint32_t*)(dsm + B_LO + off + 4) = l1;
        }
        __syncthreads();

        #pragma unroll
        for (int k16 = 0; k16 < KC / 16; k16++) {
            const int kb = k16 * 16;
            uint32_t ahi[2][4], alo[2][4], bhi[4][2], blo[4][2];
            #pragma unroll
            for (int mi = 0; mi < 2; mi++) {
                int row = mbase + mi * 16 + ((matid & 1) << 3) + rowin;
                uint32_t off = row * AST + (kb + ((matid >> 1) << 3)) * 2;
                ldsm_x4(ahi[mi], sb + A_HI + off);
                ldsm_x4(alo[mi], sb + A_LO + off);
            }
            #pragma unroll
            for (int ni = 0; ni < 4; ni++) {
                int nrow = nbase + ni * 8 + rowin;
                uint32_t off = nrow * AST + (kb + ((matid & 1) << 3)) * 2;
                ldsm_x2(bhi[ni], sb + B_HI + off);
                ldsm_x2(blo[ni], sb + B_LO + off);
            }
            #pragma unroll
            for (int mi = 0; mi < 2; mi++)
                #pragma unroll
                for (int ni = 0; ni < 4; ni++) {
                    mma_bf16(acc[mi][ni], ahi[mi], bhi[ni]);
                    mma_bf16(acc[mi][ni], ahi[mi], blo[ni]);
                    mma_bf16(acc[mi][ni], alo[mi], bhi[ni]);
                }
        }
        __syncthreads();
    }

    // epilogue: sector-aligned float2 stores
    const int qr = lid >> 2, qc = (lid & 3) * 2;
    #pragma unroll
    for (int mi = 0; mi < 2; mi++)
        #pragma unroll
        for (int ni = 0; ni < 4; ni++) {
            int col   = nbase + ni * 8 + qc;
            int node0 = rowsBase + mbase + mi * 16 + qr;
            if (node0 < N_NODES)
                *(float2*)&g_Xp[(size_t)node0 * OUT_CH + col] =
                    make_float2(acc[mi][ni][0], acc[mi][ni][1]);
            int node1 = node0 + 8;
            if (node1 < N_NODES)
                *(float2*)&g_Xp[(size_t)node1 * OUT_CH + col] =
                    make_float2(acc[mi][ni][2], acc[mi][ni][3]);
        }
}

// ---------------------------------------------------------------------------
// Direct scatter into 64-slot padded row bins. Column is stored PRE-SCALED to
// the byte offset of its Xp row (col * OUT_CH * 4) so the SpMM inner loop does
// a single 32-bit add for addressing. Overflow -> exact spill path.
// ---------------------------------------------------------------------------
__global__ __launch_bounds__(256) void scatter_direct_kernel(
    const void* __restrict__ rows, const void* __restrict__ cols,
    const float* __restrict__ vals, int nnz)
{
    int e0 = (blockIdx.x * blockDim.x + threadIdx.x) * 4;
    if (e0 >= nnz) return;
    int n = nnz - e0; if (n > 4) n = 4;
    int r[4], c[4];
    if (g_idx64) {
        const long long* pr = (const long long*)rows + e0;
        const long long* pc = (const long long*)cols + e0;
        #pragma unroll
        for (int i = 0; i < 4; i++) {
            r[i] = (i < n) ? (int)pr[i] : -1;
            c[i] = (i < n) ? (int)pc[i] : 0;
        }
    } else {
        const int* pr = (const int*)rows + e0;
        const int* pc = (const int*)cols + e0;
        #pragma unroll
        for (int i = 0; i < 4; i++) {
            r[i] = (i < n) ? pr[i] : -1;
            c[i] = (i < n) ? pc[i] : 0;
        }
    }
    float v[4];
    #pragma unroll
    for (int i = 0; i < 4; i++) v[i] = (i < n) ? vals[e0 + i] : 0.f;
    #pragma unroll
    for (int i = 0; i < 4; i++) {
        if (r[i] >= 0) {
            int pos = atomicAdd(&g_cursor[r[i]], 1);
            if (pos < SLOTS) {
                g_edge[(size_t)r[i] * SLOTS + pos] =
                    make_int2(c[i] * (OUT_CH * 4), __float_as_int(v[i]));
            } else {
                int s = atomicAdd(&g_spillcnt, 1);
                g_spill[s] = make_int4(r[i], c[i], __float_as_int(v[i]), 0);
            }
        }
    }
}

// ---------------------------------------------------------------------------
// Row SpMM: one warp per row, fp32 gathers (float2/lane, no cvt), int4 edge
// loads (2 edges / 16B uniform load), pre-scaled byte-offset addressing,
// 2-edge unroll, single store per row.
// ---------------------------------------------------------------------------
__global__ __launch_bounds__(256) void rowspmm_kernel(float* __restrict__ out)
{
    int row = blockIdx.x * 8 + (threadIdx.x >> 5);
    int lid = threadIdx.x & 31;
    if (row >= N_NODES) return;

    int cnt = g_cursor[row];
    if (cnt > SLOTS) cnt = SLOTS;
    const int2* edges = &g_edge[(size_t)row * SLOTS];   // 512B-aligned bin
    const char* base  = (const char*)g_Xp + lid * 8;    // per-lane fp32 pair

    float2 a0 = make_float2(0.f, 0.f), a1 = a0;
    int e = 0;
    for (; e + 1 < cnt; e += 2) {
        int4 ee = *(const int4*)&edges[e];              // 2 edges, aligned
        float2 x0 = *(const float2*)(base + (uint32_t)ee.x);
        float2 x1 = *(const float2*)(base + (uint32_t)ee.z);
        float v0 = __int_as_float(ee.y), v1 = __int_as_float(ee.w);
        a0.x += v0 * x0.x; a0.y += v0 * x0.y;
        a1.x += v1 * x1.x; a1.y += v1 * x1.y;
    }
    if (e < cnt) {
        int2 ee = edges[e];
        float2 x = *(const float2*)(base + (uint32_t)ee.x);
        float v = __int_as_float(ee.y);
        a0.x += v * x.x; a0.y += v * x.y;
    }
    a0.x += a1.x; a0.y += a1.y;
    *(float2*)&out[(size_t)row * OUT_CH + lid * 2] = a0;
}

// ---------------------------------------------------------------------------
// Spill drain: exact handling for rows whose degree exceeded SLOTS.
// Expected count is 0; exits immediately in that case.
// ---------------------------------------------------------------------------
__global__ __launch_bounds__(128) void spill_kernel(float* __restrict__ out)
{
    int n = g_spillcnt;
    for (int i = blockIdx.x * blockDim.x + threadIdx.x; i < n;
         i += gridDim.x * blockDim.x) {
        int4 s = g_spill[i];
        int r = s.x, c = s.y;
        float v = __int_as_float(s.z);
        const float* src = &g_Xp[(size_t)c * OUT_CH];
        float* dst = &out[(size_t)r * OUT_CH];
        for (int ch = 0; ch < OUT_CH; ch++)
            atomicAdd(&dst[ch], v * src[ch]);
    }
}

// ---------------------------------------------------------------------------
// Inputs (metadata order): g1, g2, X, W_lin, L_rows, L_cols, L_vals
// GEMM on a second stream, overlapped with init + direct scatter.
// ---------------------------------------------------------------------------
extern "C" void kernel_launch(void* const* d_in, const int* in_sizes, int n_in,
                              void* d_out, int out_size)
{
    const float* X    = (const float*)d_in[2];
    const float* W    = (const float*)d_in[3];
    const void*  rows = d_in[4];
    const void*  cols = d_in[5];
    const float* vals = (const float*)d_in[6];
    const int    nnz  = in_sizes[6];
    float*       out  = (float*)d_out;

    static cudaStream_t s2 = nullptr;
    static cudaEvent_t  evFork = nullptr, evJoin = nullptr;
    if (!s2) {
        cudaStreamCreateWithFlags(&s2, cudaStreamNonBlocking);
        cudaEventCreateWithFlags(&evFork, cudaEventDisableTiming);
        cudaEventCreateWithFlags(&evJoin, cudaEventDisableTiming);
        cudaFuncSetAttribute(gemm_mma_kernel,
                             cudaFuncAttributeMaxDynamicSharedMemorySize, GEMM_SMEM);
    }

    // Fork: GEMM branch on s2 (independent of the scatter chain)
    cudaEventRecord(evFork, 0);
    cudaStreamWaitEvent(s2, evFork, 0);
    gemm_mma_kernel<<<(N_NODES + TILE_M - 1) / TILE_M, 256, GEMM_SMEM, s2>>>(X, W);
    cudaEventRecord(evJoin, s2);

    // Binning on the main (captured) stream: init + ONE scatter pass
    const int eb4 = (nnz + 1023) / 1024;               // 4 edges / thread
    init_kernel<<<(N_NODES + 255) / 256, 256>>>((const long long*)rows, nnz);
    scatter_direct_kernel<<<eb4, 256>>>(rows, cols, vals, nnz);

    // Join: rowspmm needs g_Xp (GEMM) + bins (scatter)
    cudaStreamWaitEvent(0, evJoin, 0);
    rowspmm_kernel<<<(N_NODES + 7) / 8, 256>>>(out);
    spill_kernel<<<32, 128>>>(out);
}

// round 14
// speedup vs baseline: 1.1887x; 1.1887x over previous
#include <cuda_runtime.h>
#include <cuda_fp16.h>
#include <cstdint>

#define N_NODES 100000
#define IN_CH   256
#define OUT_CH  64
#define NNZ_MAX 1600000
#define SLOTS   64          // fixed edge slots per row (deg ~ Poisson(16))

// ---------------------------------------------------------------------------
// Static device scratch (no allocations allowed)
// ---------------------------------------------------------------------------
__device__ float g_Xp[(size_t)N_NODES * OUT_CH];       // fp32 projected features
__device__ int   g_idx64;
__device__ int   g_cursor[N_NODES];                    // per-row fill counters
__device__ int2  g_edge[(size_t)N_NODES * SLOTS];      // bins {colByteOff, val}
__device__ int   g_spillcnt;
__device__ int4  g_spill[NNZ_MAX];                     // overflow {row, col, val, 0}

// ---------------------------------------------------------------------------
// helpers
// ---------------------------------------------------------------------------
__device__ __forceinline__ uint32_t smem_u32(const void* p) {
    uint32_t a;
    asm("{ .reg .u64 t; cvta.to.shared.u64 t, %1; cvt.u32.u64 %0, t; }"
        : "=r"(a) : "l"(p));
    return a;
}

__device__ __forceinline__ void ldsm_x4(uint32_t* r, uint32_t addr) {
    asm volatile("ldmatrix.sync.aligned.m8n8.x4.shared.b16 {%0,%1,%2,%3}, [%4];"
                 : "=r"(r[0]), "=r"(r[1]), "=r"(r[2]), "=r"(r[3]) : "r"(addr));
}
__device__ __forceinline__ void ldsm_x2(uint32_t* r, uint32_t addr) {
    asm volatile("ldmatrix.sync.aligned.m8n8.x2.shared.b16 {%0,%1}, [%2];"
                 : "=r"(r[0]), "=r"(r[1]) : "r"(addr));
}
__device__ __forceinline__ void mma_fp16(float* c, const uint32_t* a, const uint32_t* b) {
    asm volatile(
        "mma.sync.aligned.m16n8k16.row.col.f32.f16.f16.f32 "
        "{%0,%1,%2,%3}, {%4,%5,%6,%7}, {%8,%9}, {%0,%1,%2,%3};"
        : "+f"(c[0]), "+f"(c[1]), "+f"(c[2]), "+f"(c[3])
        : "r"(a[0]), "r"(a[1]), "r"(a[2]), "r"(a[3]), "r"(b[0]), "r"(b[1]));
}

// pack two fp32 into one half2 register (x -> low half)
__device__ __forceinline__ uint32_t pack2(float a, float b) {
    __half2 h = __floats2half2_rn(a, b);
    return *(uint32_t*)&h;
}

// ---------------------------------------------------------------------------
// init: zero cursors + spill counter, detect int64-vs-int32 indices (block 0)
// ---------------------------------------------------------------------------
__global__ __launch_bounds__(256) void init_kernel(const long long* __restrict__ rows,
                                                   int nnz)
{
    int i = blockIdx.x * blockDim.x + threadIdx.x;
    if (i < N_NODES) g_cursor[i] = 0;
    if (i == 0) g_spillcnt = 0;

    if (blockIdx.x == 0) {
        __shared__ int ok;
        if (threadIdx.x == 0) ok = 1;
        __syncthreads();
        int nchk = 256;
        if (nnz < 512) nchk = nnz / 2;
        if ((int)threadIdx.x < nchk) {
            long long v = rows[threadIdx.x];
            if (v < 0 || v >= N_NODES) ok = 0;
        }
        __syncthreads();
        if (threadIdx.x == 0) g_idx64 = ok;
    }
}

// ---------------------------------------------------------------------------
// GEMM: Xp = X @ W^T via SINGLE-PASS fp16 mma.sync (fp32 accumulate).
// 3x fewer HMMA than the bf16x3 scheme (sm_103a throttles legacy HMMA, so
// HMMA count is the binding resource). Error ~3e-4 norm-relative (fp16 input
// rounding with measured sum-cancellation), well under the 1e-3 gate.
// Block tile 128 x 64, 8 warps of 32x32, K chunked at 128.
// Smem rows padded to 272 B -> conflict-free ldmatrix. 52 KB -> 4 CTAs/SM.
// ---------------------------------------------------------------------------
#define TILE_M 128
#define KC     128
#define AST    272
#define A_T    0
#define B_T    34816
#define GEMM_SMEM 52224

__global__ __launch_bounds__(256) void gemm_mma_kernel(const float* __restrict__ X,
                                                       const float* __restrict__ W)
{
    extern __shared__ char dsm[];
    const uint32_t sb = smem_u32(dsm);

    const int tid = threadIdx.x;
    const int wid = tid >> 5, lid = tid & 31;
    const int rowsBase = blockIdx.x * TILE_M;
    const int warpM = wid & 3, warpN = wid >> 2;
    const int mbase = warpM * 32, nbase = warpN * 32;

    float acc[2][4][4] = {};
    const int matid = lid >> 3, rowin = lid & 7;

    for (int kc = 0; kc < IN_CH / KC; kc++) {
        // X chunk: 128 rows x 128 k (4096 float4, 16/thread)
        #pragma unroll 4
        for (int i = 0; i < 16; i++) {
            int idx = i * 256 + tid;
            int r = idx >> 5, kq = idx & 31;
            int node = rowsBase + r;
            float4 x = make_float4(0.f, 0.f, 0.f, 0.f);
            if (node < N_NODES)
                x = *(const float4*)&X[(size_t)node * IN_CH + kc * KC + kq * 4];
            uint32_t off = r * AST + kq * 8;
            *(uint32_t*)(dsm + A_T + off)     = pack2(x.x, x.y);
            *(uint32_t*)(dsm + A_T + off + 4) = pack2(x.z, x.w);
        }
        // W chunk: 64 rows x 128 k (2048 float4, 8/thread)
        #pragma unroll 4
        for (int i = 0; i < 8; i++) {
            int idx = i * 256 + tid;
            int r = idx >> 5, kq = idx & 31;
            float4 x = *(const float4*)&W[(size_t)r * IN_CH + kc * KC + kq * 4];
            uint32_t off = r * AST + kq * 8;
            *(uint32_t*)(dsm + B_T + off)     = pack2(x.x, x.y);
            *(uint32_t*)(dsm + B_T + off + 4) = pack2(x.z, x.w);
        }
        __syncthreads();

        #pragma unroll
        for (int k16 = 0; k16 < KC / 16; k16++) {
            const int kb = k16 * 16;
            uint32_t a[2][4], b[4][2];
            #pragma unroll
            for (int mi = 0; mi < 2; mi++) {
                int row = mbase + mi * 16 + ((matid & 1) << 3) + rowin;
                uint32_t off = row * AST + (kb + ((matid >> 1) << 3)) * 2;
                ldsm_x4(a[mi], sb + A_T + off);
            }
            #pragma unroll
            for (int ni = 0; ni < 4; ni++) {
                int nrow = nbase + ni * 8 + rowin;
                uint32_t off = nrow * AST + (kb + ((matid & 1) << 3)) * 2;
                ldsm_x2(b[ni], sb + B_T + off);
            }
            #pragma unroll
            for (int mi = 0; mi < 2; mi++)
                #pragma unroll
                for (int ni = 0; ni < 4; ni++)
                    mma_fp16(acc[mi][ni], a[mi], b[ni]);
        }
        __syncthreads();
    }

    // epilogue: sector-aligned float2 stores
    const int qr = lid >> 2, qc = (lid & 3) * 2;
    #pragma unroll
    for (int mi = 0; mi < 2; mi++)
        #pragma unroll
        for (int ni = 0; ni < 4; ni++) {
            int col   = nbase + ni * 8 + qc;
            int node0 = rowsBase + mbase + mi * 16 + qr;
            if (node0 < N_NODES)
                *(float2*)&g_Xp[(size_t)node0 * OUT_CH + col] =
                    make_float2(acc[mi][ni][0], acc[mi][ni][1]);
            int node1 = node0 + 8;
            if (node1 < N_NODES)
                *(float2*)&g_Xp[(size_t)node1 * OUT_CH + col] =
                    make_float2(acc[mi][ni][2], acc[mi][ni][3]);
        }
}

// ---------------------------------------------------------------------------
// Direct scatter into 64-slot padded row bins. Column stored PRE-SCALED to
// the byte offset of its Xp row. Overflow -> exact spill path.
// ---------------------------------------------------------------------------
__global__ __launch_bounds__(256) void scatter_direct_kernel(
    const void* __restrict__ rows, const void* __restrict__ cols,
    const float* __restrict__ vals, int nnz)
{
    int e0 = (blockIdx.x * blockDim.x + threadIdx.x) * 4;
    if (e0 >= nnz) return;
    int n = nnz - e0; if (n > 4) n = 4;
    int r[4], c[4];
    if (g_idx64) {
        const long long* pr = (const long long*)rows + e0;
        const long long* pc = (const long long*)cols + e0;
        #pragma unroll
        for (int i = 0; i < 4; i++) {
            r[i] = (i < n) ? (int)pr[i] : -1;
            c[i] = (i < n) ? (int)pc[i] : 0;
        }
    } else {
        const int* pr = (const int*)rows + e0;
        const int* pc = (const int*)cols + e0;
        #pragma unroll
        for (int i = 0; i < 4; i++) {
            r[i] = (i < n) ? pr[i] : -1;
            c[i] = (i < n) ? pc[i] : 0;
        }
    }
    float v[4];
    #pragma unroll
    for (int i = 0; i < 4; i++) v[i] = (i < n) ? vals[e0 + i] : 0.f;
    #pragma unroll
    for (int i = 0; i < 4; i++) {
        if (r[i] >= 0) {
            int pos = atomicAdd(&g_cursor[r[i]], 1);
            if (pos < SLOTS) {
                g_edge[(size_t)r[i] * SLOTS + pos] =
                    make_int2(c[i] * (OUT_CH * 4), __float_as_int(v[i]));
            } else {
                int s = atomicAdd(&g_spillcnt, 1);
                g_spill[s] = make_int4(r[i], c[i], __float_as_int(v[i]), 0);
            }
        }
    }
}

// ---------------------------------------------------------------------------
// Row SpMM: one warp per row, fp32 gathers (float2/lane), int4 edge loads,
// byte-offset addressing, 2-edge unroll, single store per row.
// ---------------------------------------------------------------------------
__global__ __launch_bounds__(256) void rowspmm_kernel(float* __restrict__ out)
{
    int row = blockIdx.x * 8 + (threadIdx.x >> 5);
    int lid = threadIdx.x & 31;
    if (row >= N_NODES) return;

    int cnt = g_cursor[row];
    if (cnt > SLOTS) cnt = SLOTS;
    const int2* edges = &g_edge[(size_t)row * SLOTS];   // 512B-aligned bin
    const char* base  = (const char*)g_Xp + lid * 8;    // per-lane fp32 pair

    float2 a0 = make_float2(0.f, 0.f), a1 = a0;
    int e = 0;
    for (; e + 1 < cnt; e += 2) {
        int4 ee = *(const int4*)&edges[e];              // 2 edges, aligned
        float2 x0 = *(const float2*)(base + (uint32_t)ee.x);
        float2 x1 = *(const float2*)(base + (uint32_t)ee.z);
        float v0 = __int_as_float(ee.y), v1 = __int_as_float(ee.w);
        a0.x += v0 * x0.x; a0.y += v0 * x0.y;
        a1.x += v1 * x1.x; a1.y += v1 * x1.y;
    }
    if (e < cnt) {
        int2 ee = edges[e];
        float2 x = *(const float2*)(base + (uint32_t)ee.x);
        float v = __int_as_float(ee.y);
        a0.x += v * x.x; a0.y += v * x.y;
    }
    a0.x += a1.x; a0.y += a1.y;
    *(float2*)&out[(size_t)row * OUT_CH + lid * 2] = a0;
}

// ---------------------------------------------------------------------------
// Spill drain: exact handling for rows whose degree exceeded SLOTS.
// ---------------------------------------------------------------------------
__global__ __launch_bounds__(128) void spill_kernel(float* __restrict__ out)
{
    int n = g_spillcnt;
    for (int i = blockIdx.x * blockDim.x + threadIdx.x; i < n;
         i += gridDim.x * blockDim.x) {
        int4 s = g_spill[i];
        int r = s.x, c = s.y;
        float v = __int_as_float(s.z);
        const float* src = &g_Xp[(size_t)c * OUT_CH];
        float* dst = &out[(size_t)r * OUT_CH];
        for (int ch = 0; ch < OUT_CH; ch++)
            atomicAdd(&dst[ch], v * src[ch]);
    }
}

// ---------------------------------------------------------------------------
// Inputs (metadata order): g1, g2, X, W_lin, L_rows, L_cols, L_vals
// GEMM on a second stream, overlapped with init + direct scatter.
// ---------------------------------------------------------------------------
extern "C" void kernel_launch(void* const* d_in, const int* in_sizes, int n_in,
                              void* d_out, int out_size)
{
    const float* X    = (const float*)d_in[2];
    const float* W    = (const float*)d_in[3];
    const void*  rows = d_in[4];
    const void*  cols = d_in[5];
    const float* vals = (const float*)d_in[6];
    const int    nnz  = in_sizes[6];
    float*       out  = (float*)d_out;

    static cudaStream_t s2 = nullptr;
    static cudaEvent_t  evFork = nullptr, evJoin = nullptr;
    if (!s2) {
        cudaStreamCreateWithFlags(&s2, cudaStreamNonBlocking);
        cudaEventCreateWithFlags(&evFork, cudaEventDisableTiming);
        cudaEventCreateWithFlags(&evJoin, cudaEventDisableTiming);
        cudaFuncSetAttribute(gemm_mma_kernel,
                             cudaFuncAttributeMaxDynamicSharedMemorySize, GEMM_SMEM);
    }

    // Fork: GEMM branch on s2 (independent of the scatter chain)
    cudaEventRecord(evFork, 0);
    cudaStreamWaitEvent(s2, evFork, 0);
    gemm_mma_kernel<<<(N_NODES + TILE_M - 1) / TILE_M, 256, GEMM_SMEM, s2>>>(X, W);
    cudaEventRecord(evJoin, s2);

    // Binning on the main (captured) stream: init + ONE scatter pass
    const int eb4 = (nnz + 1023) / 1024;               // 4 edges / thread
    init_kernel<<<(N_NODES + 255) / 256, 256>>>((const long long*)rows, nnz);
    scatter_direct_kernel<<<eb4, 256>>>(rows, cols, vals, nnz);

    // Join: rowspmm needs g_Xp (GEMM) + bins (scatter)
    cudaStreamWaitEvent(0, evJoin, 0);
    rowspmm_kernel<<<(N_NODES + 7) / 8, 256>>>(out);
    spill_kernel<<<32, 128>>>(out);
}